// round 14
// baseline (speedup 1.0000x reference)
#include <cuda_runtime.h>
#include <cuda_bf16.h>
#include <cuda_fp16.h>

// Shapes (fixed): B=16, TE=TD=128, H=256
#define Bsz 16
#define TT 128
#define HH 256
#define MROWS (Bsz*TT)   // 2048

typedef unsigned long long u64;
typedef unsigned int u32;

// Scratch (device globals; no allocation allowed)
__device__ float  g_enc[MROWS*HH];        // orthogonalized encoder [B*TE][H] (f32)
__device__ __half g_wasH[MROWS*HH];       // (ortho_enc @ W_a)^T as f16: [b][h][e]
__device__ u32    g_uahS[Bsz*HH*128];     // (dec @ U_a)^T as splat-half2: [b][h][d]

__device__ __forceinline__ u64 pack2(float lo, float hi) {
    u64 r; asm("mov.b64 %0, {%1, %2};" : "=l"(r) : "f"(lo), "f"(hi)); return r;
}
__device__ __forceinline__ void unpack2(u64 v, float& a, float& b) {
    asm("mov.b64 {%0, %1}, %2;" : "=f"(a), "=f"(b) : "l"(v));
}
__device__ __forceinline__ void fma2(u64& d, u64 a, u64 b) {
    asm("fma.rn.f32x2 %0, %1, %2, %0;" : "+l"(d) : "l"(a), "l"(b));
}
__device__ __forceinline__ u32 hadd2u(u32 a, u32 b) {
    u32 r; asm("add.rn.f16x2 %0, %1, %2;" : "=r"(r) : "r"(a), "r"(b)); return r;
}
__device__ __forceinline__ u32 htanh2(u32 a) {
    u32 r; asm("tanh.approx.f16x2 %0, %1;" : "=r"(r) : "r"(a)); return r;
}

// ---------------------------------------------------------------------------
// K1: two GEMMs with FUSED ortho. BM=128 BN=64 BK=32, 8x4 microtile, 256 thr,
// grid (16, 4, 2).
// z=0: ortho(enc) @ W_a -> g_wasH (f16, [b][h][e]); ortho computed in-place
//      on the staged As tile (exclusive cumsum over t per h column, o = x - s,
//      the elementwise identity of x - ((x*s)/(x*x))*x). nb==0 CTAs also
//      write the ortho'd tile back to g_enc (coalesced) for K2's context.
// z=1: dec @ U_a -> g_uahS (splat-half2, [b][h][d]).
// ---------------------------------------------------------------------------
#define BMP 132
#define BNP 68
__global__ __launch_bounds__(256) void gemm2_kernel(const float* __restrict__ enc,
                                                    const float* __restrict__ dec,
                                                    const float* __restrict__ Wa,
                                                    const float* __restrict__ Ua) {
    const float *A, *W;
    if (blockIdx.z == 0) { A = enc; W = Wa; }
    else                 { A = dec; W = Ua; }

    __shared__ __align__(16) float As[32 * BMP];
    __shared__ __align__(16) float Bs[32 * BNP];
    __shared__ float scr[256];

    int tid = threadIdx.x;
    int mblk = blockIdx.x * 128;
    int nblk = blockIdx.y * 64;

    float4 pa[4], pb[2];

    #define LOADT(kt) { \
        _Pragma("unroll") \
        for (int q = 0; q < 4; q++) { int s = tid + q * 256; int m = s >> 3, kq = s & 7; \
            pa[q] = *(const float4*)&A[(size_t)(mblk + m) * HH + (kt) * 32 + kq * 4]; } \
        _Pragma("unroll") \
        for (int q = 0; q < 2; q++) { int s = tid + q * 256; int k = s >> 4, nq = s & 15; \
            pb[q] = *(const float4*)&W[(size_t)((kt) * 32 + k) * HH + nblk + nq * 4]; } }

    int tr = tid >> 4, tc = tid & 15;
    int m0 = tr * 8, n0 = tc * 4;
    u64 acc2[4][4] = {};   // 4 m-pairs x 4 n

    LOADT(0);
    for (int kt = 0; kt < 8; kt++) {
        __syncthreads();
        #pragma unroll
        for (int q = 0; q < 4; q++) {
            int s = tid + q * 256; int m = s >> 3, kq = s & 7;
            As[(kq * 4 + 0) * BMP + m] = pa[q].x;
            As[(kq * 4 + 1) * BMP + m] = pa[q].y;
            As[(kq * 4 + 2) * BMP + m] = pa[q].z;
            As[(kq * 4 + 3) * BMP + m] = pa[q].w;
        }
        #pragma unroll
        for (int q = 0; q < 2; q++) {
            int s = tid + q * 256; int k = s >> 4, nq = s & 15;
            *(float4*)&Bs[k * BNP + nq * 4] = pb[q];
        }
        __syncthreads();
        if (kt < 7) LOADT(kt + 1);

        if (blockIdx.z == 0) {
            // ---- fused ortho: exclusive cumsum over m (=t) per As row (=h) ----
            int row = tid >> 3, sg = tid & 7;       // 32 rows x 8 segs x 16 m
            float* Ar = As + row * BMP + sg * 16;
            float psum = 0.f;
            #pragma unroll
            for (int i = 0; i < 16; i++) psum += Ar[i];
            scr[row * 8 + sg] = psum;
            __syncthreads();
            float run = 0.f;
            #pragma unroll
            for (int s = 0; s < 8; s++) if (s < sg) run += scr[row * 8 + s];
            #pragma unroll
            for (int i = 0; i < 16; i++) {
                float x = Ar[i];
                Ar[i] = x - run;
                run += x;
            }
            __syncthreads();
            if (blockIdx.y == 0) {
                // writeback ortho'd tile to g_enc (coalesced float4 per warp row)
                #pragma unroll
                for (int q = 0; q < 4; q++) {
                    int s = tid + q * 256;
                    int m = s >> 3, kq = s & 7;
                    float4 o;
                    o.x = As[(kq * 4 + 0) * BMP + m];
                    o.y = As[(kq * 4 + 1) * BMP + m];
                    o.z = As[(kq * 4 + 2) * BMP + m];
                    o.w = As[(kq * 4 + 3) * BMP + m];
                    *(float4*)&g_enc[(size_t)(mblk + m) * HH + kt * 32 + kq * 4] = o;
                }
            }
        }

        #pragma unroll
        for (int kk = 0; kk < 32; kk++) {
            ulonglong2 aA = *(const ulonglong2*)&As[kk * BMP + m0];
            ulonglong2 aB = *(const ulonglong2*)&As[kk * BMP + m0 + 4];
            float4 bb = *(const float4*)&Bs[kk * BNP + n0];
            u64 am2[4] = {aA.x, aA.y, aB.x, aB.y};
            u64 bn2[4] = {pack2(bb.x, bb.x), pack2(bb.y, bb.y),
                          pack2(bb.z, bb.z), pack2(bb.w, bb.w)};
            #pragma unroll
            for (int i = 0; i < 4; i++)
                #pragma unroll
                for (int j = 0; j < 4; j++)
                    fma2(acc2[i][j], am2[i], bn2[j]);
        }
    }
    #undef LOADT

    int bb = mblk >> 7;   // one batch per mblk (128 rows)
    if (blockIdx.z == 0) {
        // f16 transposed store: g_wasH[b][h][e]; e = m0..m0+7 contiguous.
        __half* baseT = g_wasH + (size_t)bb * (HH * TT);
        #pragma unroll
        for (int j = 0; j < 4; j++) {
            float v[8];
            #pragma unroll
            for (int i = 0; i < 4; i++) unpack2(acc2[i][j], v[2 * i], v[2 * i + 1]);
            __half2 h01 = __floats2half2_rn(v[0], v[1]);
            __half2 h23 = __floats2half2_rn(v[2], v[3]);
            __half2 h45 = __floats2half2_rn(v[4], v[5]);
            __half2 h67 = __floats2half2_rn(v[6], v[7]);
            uint4 q = {*(u32*)&h01, *(u32*)&h23, *(u32*)&h45, *(u32*)&h67};
            *(uint4*)&baseT[(size_t)(nblk + n0 + j) * TT + m0] = q;
        }
    } else {
        // splat-half2 transposed store: g_uahS[b][h][d]; d = m0..m0+7 contiguous.
        u32* baseS = g_uahS + (size_t)bb * (HH * 128);
        #pragma unroll
        for (int j = 0; j < 4; j++) {
            float v[8];
            #pragma unroll
            for (int i = 0; i < 4; i++) unpack2(acc2[i][j], v[2 * i], v[2 * i + 1]);
            u32 s[8];
            #pragma unroll
            for (int q = 0; q < 8; q++) {
                __half2 hh = __half2half2(__float2half_rn(v[q]));
                s[q] = *(u32*)&hh;
            }
            u32* col = baseS + (size_t)(nblk + n0 + j) * 128 + m0;
            uint4 q0 = {s[0], s[1], s[2], s[3]};
            uint4 q1 = {s[4], s[5], s[6], s[7]};
            *(uint4*)col = q0;
            *(uint4*)(col + 4) = q1;
        }
    }
}

// ---------------------------------------------------------------------------
// K2 (fused): energy + softmax + context. grid (8 dblocks, 16 b), block 512.
// Energy inner loop on the f16x2 path (R13 proven).
// ---------------------------------------------------------------------------
#define WHP 132   // was_h row pad (halves)
__global__ __launch_bounds__(512) void energy_ctx_kernel(const float* __restrict__ Va,
                                                         float* __restrict__ eo,
                                                         float* __restrict__ co) {
    extern __shared__ __align__(16) char smraw[];
    __half* was_h = (__half*)smraw;                 // 256*132 halves = 67584 B
    u32*    uah_s = (u32*)(smraw + 67584);          // 256*20 u32 = 20480 B
    float*  Vs    = (float*)(smraw + 88064);        // 256 f32
    float*  Es = (float*)smraw;                     // overlay: [128 e][256 h]
    float*  Pt = (float*)(smraw + 131072);          // [16 d][128 e]

    int db = blockIdx.x;
    int b  = blockIdx.y;
    int tid = threadIdx.x;

    const u32* wsrc = (const u32*)(g_wasH + (size_t)b * (HH * TT));
    for (int idx = tid; idx < (HH * TT) / 2; idx += 512) {
        int h = idx >> 6, ep = idx & 63;
        *(u32*)&was_h[h * WHP + ep * 2] = wsrc[idx];
    }
    const u32* usrc = g_uahS + (size_t)b * (HH * 128) + db * 16;
    for (int idx = tid; idx < 16 * HH; idx += 512) {
        int h = idx >> 4, dd = idx & 15;
        uah_s[h * 20 + dd] = usrc[h * 128 + dd];
    }
    if (tid < 256) Vs[tid] = Va[tid];
    __syncthreads();

    int eg = tid & 31, dg = tid >> 5;    // dg = warp = d-row (0..15)
    int e0 = eg * 4;
    const __half* wp = was_h + e0;
    const u32* up = uah_s + dg;

    float a0 = 0.f, a1 = 0.f, a2 = 0.f, a3 = 0.f;
    #pragma unroll 4
    for (int h = 0; h < HH; h++) {
        uint2 wv = *(const uint2*)(wp + h * WHP);
        u32 u2 = up[h * 20];
        u32 s0 = hadd2u(u2, wv.x);
        u32 s1 = hadd2u(u2, wv.y);
        u32 t0 = htanh2(s0);
        u32 t1 = htanh2(s1);
        float v = Vs[h];
        float2 f0 = __half22float2(*(__half2*)&t0);
        float2 f1 = __half22float2(*(__half2*)&t1);
        a0 += v * f0.x;
        a1 += v * f0.y;
        a2 += v * f1.x;
        a3 += v * f1.y;
    }

    float m = fmaxf(fmaxf(a0, a1), fmaxf(a2, a3));
    #pragma unroll
    for (int o = 16; o > 0; o >>= 1) m = fmaxf(m, __shfl_xor_sync(0xffffffffu, m, o));
    float x0 = __expf(a0 - m), x1 = __expf(a1 - m);
    float x2 = __expf(a2 - m), x3 = __expf(a3 - m);
    float ssum = x0 + x1 + x2 + x3;
    #pragma unroll
    for (int o = 16; o > 0; o >>= 1) ssum += __shfl_xor_sync(0xffffffffu, ssum, o);
    float inv = 1.f / ssum;
    float4 p4 = {x0 * inv, x1 * inv, x2 * inv, x3 * inv};
    *(float4*)&eo[(size_t)(b * TT + db * 16 + dg) * TT + e0] = p4;

    // ---- context ----
    __syncthreads();

    *(float4*)&Pt[dg * 128 + e0] = p4;
    #pragma unroll
    for (int t = tid; t < (TT * HH) / 4; t += 512) {
        int e = t >> 6, hq = t & 63;
        *(float4*)&Es[e * HH + hq * 4] =
            *(const float4*)&g_enc[(size_t)(b * TT + e) * HH + hq * 4];
    }
    __syncthreads();

    int mp = tid >> 6, tc2 = tid & 63;
    int m0 = mp * 2, n0 = tc2 * 4;
    const float* p0r = Pt + m0 * 128;
    const float* p1r = Pt + (m0 + 1) * 128;
    const float* er  = Es + n0;

    u64 acc2[2][2] = {};
    #pragma unroll 4
    for (int k = 0; k < 128; k++) {
        float pv0 = p0r[k];
        float pv1 = p1r[k];
        ulonglong2 ev = *(const ulonglong2*)(er + k * HH);
        u64 pa0 = pack2(pv0, pv0);
        u64 pa1 = pack2(pv1, pv1);
        fma2(acc2[0][0], pa0, ev.x); fma2(acc2[0][1], pa0, ev.y);
        fma2(acc2[1][0], pa1, ev.x); fma2(acc2[1][1], pa1, ev.y);
    }

    #pragma unroll
    for (int i = 0; i < 2; i++) {
        float l0, h0, l1, h1;
        unpack2(acc2[i][0], l0, h0);
        unpack2(acc2[i][1], l1, h1);
        float4 r = {l0, h0, l1, h1};
        *(float4*)&co[(size_t)(b * TT + db * 16 + m0 + i) * HH + n0] = r;
    }
}

// ---------------------------------------------------------------------------
extern "C" void kernel_launch(void* const* d_in, const int* in_sizes, int n_in,
                              void* d_out, int out_size) {
    const float* enc = (const float*)d_in[0];
    const float* dec = (const float*)d_in[1];
    const float* Wa  = (const float*)d_in[2];
    const float* Ua  = (const float*)d_in[3];
    const float* Va  = (const float*)d_in[4];

    float* co = (float*)d_out;                    // c_outputs [16,128,256]
    float* eo = co + Bsz * TT * HH;               // e_outputs [16,128,128]

    const int SM3 = 131072 + 8192;                // 139264 B
    static bool attr_done = false;
    if (!attr_done) {
        cudaFuncSetAttribute(energy_ctx_kernel,
                             cudaFuncAttributeMaxDynamicSharedMemorySize, SM3);
        attr_done = true;
    }

    gemm2_kernel<<<dim3(16, 4, 2), 256>>>(enc, dec, Wa, Ua);
    energy_ctx_kernel<<<dim3(8, 16), 512, SM3>>>(Va, eo, co);
}

// round 15
// speedup vs baseline: 1.0924x; 1.0924x over previous
#include <cuda_runtime.h>
#include <cuda_bf16.h>
#include <cuda_fp16.h>

// Shapes (fixed): B=16, TE=TD=128, H=256
#define Bsz 16
#define TT 128
#define HH 256
#define MROWS (Bsz*TT)   // 2048

typedef unsigned long long u64;
typedef unsigned int u32;

// Scratch (device globals; no allocation allowed)
__device__ float  g_enc[MROWS*HH];        // orthogonalized encoder [B*TE][H] (f32)
__device__ __half g_wasH[MROWS*HH];       // (ortho_enc @ W_a)^T as f16: [b][h][e]
__device__ u32    g_uahS[Bsz*HH*128];     // (dec @ U_a)^T as splat-half2: [b][h][d]

__device__ __forceinline__ u64 pack2(float lo, float hi) {
    u64 r; asm("mov.b64 %0, {%1, %2};" : "=l"(r) : "f"(lo), "f"(hi)); return r;
}
__device__ __forceinline__ void unpack2(u64 v, float& a, float& b) {
    asm("mov.b64 {%0, %1}, %2;" : "=f"(a), "=f"(b) : "l"(v));
}
__device__ __forceinline__ void fma2(u64& d, u64 a, u64 b) {
    asm("fma.rn.f32x2 %0, %1, %2, %0;" : "+l"(d) : "l"(a), "l"(b));
}
__device__ __forceinline__ u32 hadd2u(u32 a, u32 b) {
    u32 r; asm("add.rn.f16x2 %0, %1, %2;" : "=r"(r) : "r"(a), "r"(b)); return r;
}
__device__ __forceinline__ u32 htanh2(u32 a) {
    u32 r; asm("tanh.approx.f16x2 %0, %1;" : "=r"(r) : "r"(a)); return r;
}

// ---------------------------------------------------------------------------
// K1: orthogonalize (proven R6/R13). out[t] = x[t] - sum_{j<t} x[j].
// grid (8 hb, 16 b), block 256 = 32 segs x 8 float4-lanes.
// ---------------------------------------------------------------------------
__global__ __launch_bounds__(256) void ortho_kernel(const float* __restrict__ enc) {
    int hb = blockIdx.x;
    int b  = blockIdx.y;
    int tid = threadIdx.x;
    int seg = tid >> 3;
    int hq  = tid & 7;
    int h = hb * 32 + hq * 4;
    int t0 = seg * 4;

    const float4* base = (const float4*)(enc + (size_t)(b * TT + t0) * HH + h);
    float4* obase = (float4*)(g_enc + (size_t)(b * TT + t0) * HH + h);

    float4 x[4];
    #pragma unroll
    for (int t = 0; t < 4; t++) x[t] = base[t * (HH / 4)];

    float4 ps;
    ps.x = x[0].x + x[1].x + x[2].x + x[3].x;
    ps.y = x[0].y + x[1].y + x[2].y + x[3].y;
    ps.z = x[0].z + x[1].z + x[2].z + x[3].z;
    ps.w = x[0].w + x[1].w + x[2].w + x[3].w;

    __shared__ float4 part[32][8];
    part[seg][hq] = ps;
    __syncthreads();

    float4 run = {0.f, 0.f, 0.f, 0.f};
    for (int s = 0; s < seg; s++) {
        float4 p = part[s][hq];
        run.x += p.x; run.y += p.y; run.z += p.z; run.w += p.w;
    }
    #pragma unroll
    for (int t = 0; t < 4; t++) {
        float4 o;
        o.x = x[t].x - run.x;
        o.y = x[t].y - run.y;
        o.z = x[t].z - run.z;
        o.w = x[t].w - run.w;
        obase[t * (HH / 4)] = o;
        run.x += x[t].x; run.y += x[t].y; run.z += x[t].z; run.w += x[t].w;
    }
}

// ---------------------------------------------------------------------------
// K2: two GEMMs (proven R13). BM=128 BN=64 BK=32, 8x4 microtile, 256 thr,
// grid (16, 4, 2).
// z=0: g_enc @ W_a -> g_wasH (f16, [b][h][e]);
// z=1: dec  @ U_a -> g_uahS (splat-half2, [b][h][d]).
// ---------------------------------------------------------------------------
#define BMP 132
#define BNP 68
__global__ __launch_bounds__(256) void gemm2_kernel(const float* __restrict__ dec,
                                                    const float* __restrict__ Wa,
                                                    const float* __restrict__ Ua) {
    const float *A, *W;
    if (blockIdx.z == 0) { A = g_enc; W = Wa; }
    else                 { A = dec;   W = Ua; }

    __shared__ __align__(16) float As[32 * BMP];
    __shared__ __align__(16) float Bs[32 * BNP];

    int tid = threadIdx.x;
    int mblk = blockIdx.x * 128;
    int nblk = blockIdx.y * 64;

    float4 pa[4], pb[2];

    #define LOADT(kt) { \
        _Pragma("unroll") \
        for (int q = 0; q < 4; q++) { int s = tid + q * 256; int m = s >> 3, kq = s & 7; \
            pa[q] = *(const float4*)&A[(size_t)(mblk + m) * HH + (kt) * 32 + kq * 4]; } \
        _Pragma("unroll") \
        for (int q = 0; q < 2; q++) { int s = tid + q * 256; int k = s >> 4, nq = s & 15; \
            pb[q] = *(const float4*)&W[(size_t)((kt) * 32 + k) * HH + nblk + nq * 4]; } }

    int tr = tid >> 4, tc = tid & 15;
    int m0 = tr * 8, n0 = tc * 4;
    u64 acc2[4][4] = {};   // 4 m-pairs x 4 n

    LOADT(0);
    for (int kt = 0; kt < 8; kt++) {
        __syncthreads();
        #pragma unroll
        for (int q = 0; q < 4; q++) {
            int s = tid + q * 256; int m = s >> 3, kq = s & 7;
            As[(kq * 4 + 0) * BMP + m] = pa[q].x;
            As[(kq * 4 + 1) * BMP + m] = pa[q].y;
            As[(kq * 4 + 2) * BMP + m] = pa[q].z;
            As[(kq * 4 + 3) * BMP + m] = pa[q].w;
        }
        #pragma unroll
        for (int q = 0; q < 2; q++) {
            int s = tid + q * 256; int k = s >> 4, nq = s & 15;
            *(float4*)&Bs[k * BNP + nq * 4] = pb[q];
        }
        __syncthreads();
        if (kt < 7) LOADT(kt + 1);

        #pragma unroll
        for (int kk = 0; kk < 32; kk++) {
            ulonglong2 aA = *(const ulonglong2*)&As[kk * BMP + m0];
            ulonglong2 aB = *(const ulonglong2*)&As[kk * BMP + m0 + 4];
            float4 bb = *(const float4*)&Bs[kk * BNP + n0];
            u64 am2[4] = {aA.x, aA.y, aB.x, aB.y};
            u64 bn2[4] = {pack2(bb.x, bb.x), pack2(bb.y, bb.y),
                          pack2(bb.z, bb.z), pack2(bb.w, bb.w)};
            #pragma unroll
            for (int i = 0; i < 4; i++)
                #pragma unroll
                for (int j = 0; j < 4; j++)
                    fma2(acc2[i][j], am2[i], bn2[j]);
        }
    }
    #undef LOADT

    int bb = mblk >> 7;
    if (blockIdx.z == 0) {
        __half* baseT = g_wasH + (size_t)bb * (HH * TT);
        #pragma unroll
        for (int j = 0; j < 4; j++) {
            float v[8];
            #pragma unroll
            for (int i = 0; i < 4; i++) unpack2(acc2[i][j], v[2 * i], v[2 * i + 1]);
            __half2 h01 = __floats2half2_rn(v[0], v[1]);
            __half2 h23 = __floats2half2_rn(v[2], v[3]);
            __half2 h45 = __floats2half2_rn(v[4], v[5]);
            __half2 h67 = __floats2half2_rn(v[6], v[7]);
            uint4 q = {*(u32*)&h01, *(u32*)&h23, *(u32*)&h45, *(u32*)&h67};
            *(uint4*)&baseT[(size_t)(nblk + n0 + j) * TT + m0] = q;
        }
    } else {
        u32* baseS = g_uahS + (size_t)bb * (HH * 128);
        #pragma unroll
        for (int j = 0; j < 4; j++) {
            float v[8];
            #pragma unroll
            for (int i = 0; i < 4; i++) unpack2(acc2[i][j], v[2 * i], v[2 * i + 1]);
            u32 s[8];
            #pragma unroll
            for (int q = 0; q < 8; q++) {
                __half2 hh = __half2half2(__float2half_rn(v[q]));
                s[q] = *(u32*)&hh;
            }
            u32* col = baseS + (size_t)(nblk + n0 + j) * 128 + m0;
            uint4 q0 = {s[0], s[1], s[2], s[3]};
            uint4 q1 = {s[4], s[5], s[6], s[7]};
            *(uint4*)col = q0;
            *(uint4*)(col + 4) = q1;
        }
    }
}

// ---------------------------------------------------------------------------
// K3 (fused): energy + softmax + context. grid (8 dblocks, 16 b), block 512.
// Energy + context inner loops use EXPLICIT 8-deep register batching so the
// LDS latency chains overlap (R14 profile: regs=32, issue=34% -> no pipeline).
// ---------------------------------------------------------------------------
#define WHP 132   // was_h row pad (halves)
__global__ __launch_bounds__(512) void energy_ctx_kernel(const float* __restrict__ Va,
                                                         float* __restrict__ eo,
                                                         float* __restrict__ co) {
    extern __shared__ __align__(16) char smraw[];
    __half* was_h = (__half*)smraw;                 // 256*132 halves = 67584 B
    u32*    uah_s = (u32*)(smraw + 67584);          // 256*20 u32 = 20480 B
    float*  Vs    = (float*)(smraw + 88064);        // 256 f32
    float*  Es = (float*)smraw;                     // overlay: [128 e][256 h]
    float*  Pt = (float*)(smraw + 131072);          // [16 d][128 e]

    int db = blockIdx.x;
    int b  = blockIdx.y;
    int tid = threadIdx.x;

    const u32* wsrc = (const u32*)(g_wasH + (size_t)b * (HH * TT));
    for (int idx = tid; idx < (HH * TT) / 2; idx += 512) {
        int h = idx >> 6, ep = idx & 63;
        *(u32*)&was_h[h * WHP + ep * 2] = wsrc[idx];
    }
    const u32* usrc = g_uahS + (size_t)b * (HH * 128) + db * 16;
    for (int idx = tid; idx < 16 * HH; idx += 512) {
        int h = idx >> 4, dd = idx & 15;
        uah_s[h * 20 + dd] = usrc[h * 128 + dd];
    }
    if (tid < 256) Vs[tid] = Va[tid];
    __syncthreads();

    int eg = tid & 31, dg = tid >> 5;    // dg = warp = d-row (0..15)
    int e0 = eg * 4;
    const __half* wp = was_h + e0;
    const u32* up = uah_s + dg;

    float a0 = 0.f, a1 = 0.f, a2 = 0.f, a3 = 0.f;
    #pragma unroll 1
    for (int hb2 = 0; hb2 < HH; hb2 += 8) {
        uint2 wv[8]; u32 uu[8]; float vv[8];
        #pragma unroll
        for (int j = 0; j < 8; j++) {
            wv[j] = *(const uint2*)(wp + (hb2 + j) * WHP);
            uu[j] = up[(hb2 + j) * 20];
            vv[j] = Vs[hb2 + j];
        }
        #pragma unroll
        for (int j = 0; j < 8; j++) {
            u32 s0 = hadd2u(uu[j], wv[j].x);
            u32 s1 = hadd2u(uu[j], wv[j].y);
            u32 t0 = htanh2(s0);
            u32 t1 = htanh2(s1);
            float2 f0 = __half22float2(*(__half2*)&t0);
            float2 f1 = __half22float2(*(__half2*)&t1);
            a0 += vv[j] * f0.x;
            a1 += vv[j] * f0.y;
            a2 += vv[j] * f1.x;
            a3 += vv[j] * f1.y;
        }
    }

    float m = fmaxf(fmaxf(a0, a1), fmaxf(a2, a3));
    #pragma unroll
    for (int o = 16; o > 0; o >>= 1) m = fmaxf(m, __shfl_xor_sync(0xffffffffu, m, o));
    float x0 = __expf(a0 - m), x1 = __expf(a1 - m);
    float x2 = __expf(a2 - m), x3 = __expf(a3 - m);
    float ssum = x0 + x1 + x2 + x3;
    #pragma unroll
    for (int o = 16; o > 0; o >>= 1) ssum += __shfl_xor_sync(0xffffffffu, ssum, o);
    float inv = 1.f / ssum;
    float4 p4 = {x0 * inv, x1 * inv, x2 * inv, x3 * inv};
    *(float4*)&eo[(size_t)(b * TT + db * 16 + dg) * TT + e0] = p4;

    // ---- context ----
    __syncthreads();

    *(float4*)&Pt[dg * 128 + e0] = p4;
    #pragma unroll
    for (int t = tid; t < (TT * HH) / 4; t += 512) {
        int e = t >> 6, hq = t & 63;
        *(float4*)&Es[e * HH + hq * 4] =
            *(const float4*)&g_enc[(size_t)(b * TT + e) * HH + hq * 4];
    }
    __syncthreads();

    int mp = tid >> 6, tc2 = tid & 63;
    int m0 = mp * 2, n0 = tc2 * 4;
    const float* p0r = Pt + m0 * 128;
    const float* p1r = Pt + (m0 + 1) * 128;
    const float* er  = Es + n0;

    u64 acc2[2][2] = {};
    #pragma unroll 1
    for (int kc = 0; kc < 128; kc += 8) {
        float pv0[8], pv1[8];
        ulonglong2 ev[8];
        #pragma unroll
        for (int j = 0; j < 8; j++) {
            ev[j]  = *(const ulonglong2*)(er + (kc + j) * HH);
            pv0[j] = p0r[kc + j];
            pv1[j] = p1r[kc + j];
        }
        #pragma unroll
        for (int j = 0; j < 8; j++) {
            u64 pa0 = pack2(pv0[j], pv0[j]);
            u64 pa1 = pack2(pv1[j], pv1[j]);
            fma2(acc2[0][0], pa0, ev[j].x); fma2(acc2[0][1], pa0, ev[j].y);
            fma2(acc2[1][0], pa1, ev[j].x); fma2(acc2[1][1], pa1, ev[j].y);
        }
    }

    #pragma unroll
    for (int i = 0; i < 2; i++) {
        float l0, h0, l1, h1;
        unpack2(acc2[i][0], l0, h0);
        unpack2(acc2[i][1], l1, h1);
        float4 r = {l0, h0, l1, h1};
        *(float4*)&co[(size_t)(b * TT + db * 16 + m0 + i) * HH + n0] = r;
    }
}

// ---------------------------------------------------------------------------
extern "C" void kernel_launch(void* const* d_in, const int* in_sizes, int n_in,
                              void* d_out, int out_size) {
    const float* enc = (const float*)d_in[0];
    const float* dec = (const float*)d_in[1];
    const float* Wa  = (const float*)d_in[2];
    const float* Ua  = (const float*)d_in[3];
    const float* Va  = (const float*)d_in[4];

    float* co = (float*)d_out;                    // c_outputs [16,128,256]
    float* eo = co + Bsz * TT * HH;               // e_outputs [16,128,128]

    const int SM3 = 131072 + 8192;                // 139264 B
    static bool attr_done = false;
    if (!attr_done) {
        cudaFuncSetAttribute(energy_ctx_kernel,
                             cudaFuncAttributeMaxDynamicSharedMemorySize, SM3);
        attr_done = true;
    }

    ortho_kernel<<<dim3(8, 16), 256>>>(enc);
    gemm2_kernel<<<dim3(16, 4, 2), 256>>>(dec, Wa, Ua);
    energy_ctx_kernel<<<dim3(8, 16), 512, SM3>>>(Va, eo, co);
}

// round 16
// speedup vs baseline: 1.1269x; 1.0316x over previous
#include <cuda_runtime.h>
#include <cuda_bf16.h>
#include <cuda_fp16.h>

// Shapes (fixed): B=16, TE=TD=128, H=256
#define Bsz 16
#define TT 128
#define HH 256
#define MROWS (Bsz*TT)   // 2048

typedef unsigned long long u64;
typedef unsigned int u32;

// Scratch (device globals; no allocation allowed)
__device__ float  g_enc[MROWS*HH];        // orthogonalized encoder [B*TE][H] (f32)
__device__ __half g_wasH[MROWS*HH];       // (ortho_enc @ W_a)^T as f16: [b][h][e]
__device__ u32    g_uahS[Bsz*HH*128];     // (dec @ U_a)^T as splat-half2: [b][h][d]

__device__ __forceinline__ u64 pack2(float lo, float hi) {
    u64 r; asm("mov.b64 %0, {%1, %2};" : "=l"(r) : "f"(lo), "f"(hi)); return r;
}
__device__ __forceinline__ void unpack2(u64 v, float& a, float& b) {
    asm("mov.b64 {%0, %1}, %2;" : "=f"(a), "=f"(b) : "l"(v));
}
__device__ __forceinline__ void fma2(u64& d, u64 a, u64 b) {
    asm("fma.rn.f32x2 %0, %1, %2, %0;" : "+l"(d) : "l"(a), "l"(b));
}
__device__ __forceinline__ u32 hadd2u(u32 a, u32 b) {
    u32 r; asm("add.rn.f16x2 %0, %1, %2;" : "=r"(r) : "r"(a), "r"(b)); return r;
}
__device__ __forceinline__ u32 htanh2(u32 a) {
    u32 r; asm("tanh.approx.f16x2 %0, %1;" : "=r"(r) : "r"(a)); return r;
}
__device__ __forceinline__ u32 hfma2u(u32 a, u32 b, u32 c) {
    u32 r; asm("fma.rn.f16x2 %0, %1, %2, %3;" : "=r"(r) : "r"(a), "r"(b), "r"(c)); return r;
}

// ---------------------------------------------------------------------------
// K1: orthogonalize (proven R6/R13). out[t] = x[t] - sum_{j<t} x[j].
// grid (8 hb, 16 b), block 256 = 32 segs x 8 float4-lanes.
// ---------------------------------------------------------------------------
__global__ __launch_bounds__(256) void ortho_kernel(const float* __restrict__ enc) {
    int hb = blockIdx.x;
    int b  = blockIdx.y;
    int tid = threadIdx.x;
    int seg = tid >> 3;
    int hq  = tid & 7;
    int h = hb * 32 + hq * 4;
    int t0 = seg * 4;

    const float4* base = (const float4*)(enc + (size_t)(b * TT + t0) * HH + h);
    float4* obase = (float4*)(g_enc + (size_t)(b * TT + t0) * HH + h);

    float4 x[4];
    #pragma unroll
    for (int t = 0; t < 4; t++) x[t] = base[t * (HH / 4)];

    float4 ps;
    ps.x = x[0].x + x[1].x + x[2].x + x[3].x;
    ps.y = x[0].y + x[1].y + x[2].y + x[3].y;
    ps.z = x[0].z + x[1].z + x[2].z + x[3].z;
    ps.w = x[0].w + x[1].w + x[2].w + x[3].w;

    __shared__ float4 part[32][8];
    part[seg][hq] = ps;
    __syncthreads();

    float4 run = {0.f, 0.f, 0.f, 0.f};
    for (int s = 0; s < seg; s++) {
        float4 p = part[s][hq];
        run.x += p.x; run.y += p.y; run.z += p.z; run.w += p.w;
    }
    #pragma unroll
    for (int t = 0; t < 4; t++) {
        float4 o;
        o.x = x[t].x - run.x;
        o.y = x[t].y - run.y;
        o.z = x[t].z - run.z;
        o.w = x[t].w - run.w;
        obase[t * (HH / 4)] = o;
        run.x += x[t].x; run.y += x[t].y; run.z += x[t].z; run.w += x[t].w;
    }
}

// ---------------------------------------------------------------------------
// K2: two GEMMs (proven R13). BM=128 BN=64 BK=32, 8x4 microtile, 256 thr,
// grid (16, 4, 2).
// z=0: g_enc @ W_a -> g_wasH (f16, [b][h][e]);
// z=1: dec  @ U_a -> g_uahS (splat-half2, [b][h][d]).
// ---------------------------------------------------------------------------
#define BMP 132
#define BNP 68
__global__ __launch_bounds__(256) void gemm2_kernel(const float* __restrict__ dec,
                                                    const float* __restrict__ Wa,
                                                    const float* __restrict__ Ua) {
    const float *A, *W;
    if (blockIdx.z == 0) { A = g_enc; W = Wa; }
    else                 { A = dec;   W = Ua; }

    __shared__ __align__(16) float As[32 * BMP];
    __shared__ __align__(16) float Bs[32 * BNP];

    int tid = threadIdx.x;
    int mblk = blockIdx.x * 128;
    int nblk = blockIdx.y * 64;

    float4 pa[4], pb[2];

    #define LOADT(kt) { \
        _Pragma("unroll") \
        for (int q = 0; q < 4; q++) { int s = tid + q * 256; int m = s >> 3, kq = s & 7; \
            pa[q] = *(const float4*)&A[(size_t)(mblk + m) * HH + (kt) * 32 + kq * 4]; } \
        _Pragma("unroll") \
        for (int q = 0; q < 2; q++) { int s = tid + q * 256; int k = s >> 4, nq = s & 15; \
            pb[q] = *(const float4*)&W[(size_t)((kt) * 32 + k) * HH + nblk + nq * 4]; } }

    int tr = tid >> 4, tc = tid & 15;
    int m0 = tr * 8, n0 = tc * 4;
    u64 acc2[4][4] = {};   // 4 m-pairs x 4 n

    LOADT(0);
    for (int kt = 0; kt < 8; kt++) {
        __syncthreads();
        #pragma unroll
        for (int q = 0; q < 4; q++) {
            int s = tid + q * 256; int m = s >> 3, kq = s & 7;
            As[(kq * 4 + 0) * BMP + m] = pa[q].x;
            As[(kq * 4 + 1) * BMP + m] = pa[q].y;
            As[(kq * 4 + 2) * BMP + m] = pa[q].z;
            As[(kq * 4 + 3) * BMP + m] = pa[q].w;
        }
        #pragma unroll
        for (int q = 0; q < 2; q++) {
            int s = tid + q * 256; int k = s >> 4, nq = s & 15;
            *(float4*)&Bs[k * BNP + nq * 4] = pb[q];
        }
        __syncthreads();
        if (kt < 7) LOADT(kt + 1);

        #pragma unroll
        for (int kk = 0; kk < 32; kk++) {
            ulonglong2 aA = *(const ulonglong2*)&As[kk * BMP + m0];
            ulonglong2 aB = *(const ulonglong2*)&As[kk * BMP + m0 + 4];
            float4 bb = *(const float4*)&Bs[kk * BNP + n0];
            u64 am2[4] = {aA.x, aA.y, aB.x, aB.y};
            u64 bn2[4] = {pack2(bb.x, bb.x), pack2(bb.y, bb.y),
                          pack2(bb.z, bb.z), pack2(bb.w, bb.w)};
            #pragma unroll
            for (int i = 0; i < 4; i++)
                #pragma unroll
                for (int j = 0; j < 4; j++)
                    fma2(acc2[i][j], am2[i], bn2[j]);
        }
    }
    #undef LOADT

    int bb = mblk >> 7;
    if (blockIdx.z == 0) {
        __half* baseT = g_wasH + (size_t)bb * (HH * TT);
        #pragma unroll
        for (int j = 0; j < 4; j++) {
            float v[8];
            #pragma unroll
            for (int i = 0; i < 4; i++) unpack2(acc2[i][j], v[2 * i], v[2 * i + 1]);
            __half2 h01 = __floats2half2_rn(v[0], v[1]);
            __half2 h23 = __floats2half2_rn(v[2], v[3]);
            __half2 h45 = __floats2half2_rn(v[4], v[5]);
            __half2 h67 = __floats2half2_rn(v[6], v[7]);
            uint4 q = {*(u32*)&h01, *(u32*)&h23, *(u32*)&h45, *(u32*)&h67};
            *(uint4*)&baseT[(size_t)(nblk + n0 + j) * TT + m0] = q;
        }
    } else {
        u32* baseS = g_uahS + (size_t)bb * (HH * 128);
        #pragma unroll
        for (int j = 0; j < 4; j++) {
            float v[8];
            #pragma unroll
            for (int i = 0; i < 4; i++) unpack2(acc2[i][j], v[2 * i], v[2 * i + 1]);
            u32 s[8];
            #pragma unroll
            for (int q = 0; q < 8; q++) {
                __half2 hh = __half2half2(__float2half_rn(v[q]));
                s[q] = *(u32*)&hh;
            }
            u32* col = baseS + (size_t)(nblk + n0 + j) * 128 + m0;
            uint4 q0 = {s[0], s[1], s[2], s[3]};
            uint4 q1 = {s[4], s[5], s[6], s[7]};
            *(uint4*)col = q0;
            *(uint4*)(col + 4) = q1;
        }
    }
}

// ---------------------------------------------------------------------------
// K3 (fused): energy + softmax + context. grid (8 dblocks, 16 b), block 512.
// Energy: HFMA2 f16x2 accumulation of V*tanh, flushed to f32 every 4 h.
// F2F (half->float cvt) per h per warp drops 4 -> 1, unloading the XU pipe.
// ---------------------------------------------------------------------------
#define WHP 132   // was_h row pad (halves)
__global__ __launch_bounds__(512) void energy_ctx_kernel(const float* __restrict__ Va,
                                                         float* __restrict__ eo,
                                                         float* __restrict__ co) {
    extern __shared__ __align__(16) char smraw[];
    __half* was_h = (__half*)smraw;                 // 256*132 halves = 67584 B
    u32*    uah_s = (u32*)(smraw + 67584);          // 256*20 u32 = 20480 B
    u32*    Vs2   = (u32*)(smraw + 88064);          // 256 splat-half2 = 1024 B
    float*  Es = (float*)smraw;                     // overlay: [128 e][256 h]
    float*  Pt = (float*)(smraw + 131072);          // [16 d][128 e]

    int db = blockIdx.x;
    int b  = blockIdx.y;
    int tid = threadIdx.x;

    const u32* wsrc = (const u32*)(g_wasH + (size_t)b * (HH * TT));
    for (int idx = tid; idx < (HH * TT) / 2; idx += 512) {
        int h = idx >> 6, ep = idx & 63;
        *(u32*)&was_h[h * WHP + ep * 2] = wsrc[idx];
    }
    const u32* usrc = g_uahS + (size_t)b * (HH * 128) + db * 16;
    for (int idx = tid; idx < 16 * HH; idx += 512) {
        int h = idx >> 4, dd = idx & 15;
        uah_s[h * 20 + dd] = usrc[h * 128 + dd];
    }
    if (tid < 256) {
        __half2 hh = __half2half2(__float2half_rn(Va[tid]));
        Vs2[tid] = *(u32*)&hh;
    }
    __syncthreads();

    int eg = tid & 31, dg = tid >> 5;    // dg = warp = d-row (0..15)
    int e0 = eg * 4;
    const __half* wp = was_h + e0;
    const u32* up = uah_s + dg;

    float a0 = 0.f, a1 = 0.f, a2 = 0.f, a3 = 0.f;
    #pragma unroll 1
    for (int hb2 = 0; hb2 < HH; hb2 += 8) {
        uint2 wv[8]; u32 uu[8]; u32 vv[8];
        #pragma unroll
        for (int j = 0; j < 8; j++) {
            wv[j] = *(const uint2*)(wp + (hb2 + j) * WHP);
            uu[j] = up[(hb2 + j) * 20];
            vv[j] = Vs2[hb2 + j];
        }
        #pragma unroll
        for (int half4 = 0; half4 < 2; half4++) {
            u32 hacc0 = 0u, hacc1 = 0u;      // f16x2 accumulators (4 h window)
            #pragma unroll
            for (int jj = 0; jj < 4; jj++) {
                int j = half4 * 4 + jj;
                u32 t0 = htanh2(hadd2u(uu[j], wv[j].x));
                u32 t1 = htanh2(hadd2u(uu[j], wv[j].y));
                hacc0 = hfma2u(t0, vv[j], hacc0);
                hacc1 = hfma2u(t1, vv[j], hacc1);
            }
            float2 f0 = __half22float2(*(__half2*)&hacc0);
            float2 f1 = __half22float2(*(__half2*)&hacc1);
            a0 += f0.x; a1 += f0.y;
            a2 += f1.x; a3 += f1.y;
        }
    }

    float m = fmaxf(fmaxf(a0, a1), fmaxf(a2, a3));
    #pragma unroll
    for (int o = 16; o > 0; o >>= 1) m = fmaxf(m, __shfl_xor_sync(0xffffffffu, m, o));
    float x0 = __expf(a0 - m), x1 = __expf(a1 - m);
    float x2 = __expf(a2 - m), x3 = __expf(a3 - m);
    float ssum = x0 + x1 + x2 + x3;
    #pragma unroll
    for (int o = 16; o > 0; o >>= 1) ssum += __shfl_xor_sync(0xffffffffu, ssum, o);
    float inv = 1.f / ssum;
    float4 p4 = {x0 * inv, x1 * inv, x2 * inv, x3 * inv};
    *(float4*)&eo[(size_t)(b * TT + db * 16 + dg) * TT + e0] = p4;

    // ---- context ----
    __syncthreads();

    *(float4*)&Pt[dg * 128 + e0] = p4;
    #pragma unroll
    for (int t = tid; t < (TT * HH) / 4; t += 512) {
        int e = t >> 6, hq = t & 63;
        *(float4*)&Es[e * HH + hq * 4] =
            *(const float4*)&g_enc[(size_t)(b * TT + e) * HH + hq * 4];
    }
    __syncthreads();

    int mp = tid >> 6, tc2 = tid & 63;
    int m0 = mp * 2, n0 = tc2 * 4;
    const float* p0r = Pt + m0 * 128;
    const float* p1r = Pt + (m0 + 1) * 128;
    const float* er  = Es + n0;

    u64 acc2[2][2] = {};
    #pragma unroll 1
    for (int kc = 0; kc < 128; kc += 8) {
        float pv0[8], pv1[8];
        ulonglong2 ev[8];
        #pragma unroll
        for (int j = 0; j < 8; j++) {
            ev[j]  = *(const ulonglong2*)(er + (kc + j) * HH);
            pv0[j] = p0r[kc + j];
            pv1[j] = p1r[kc + j];
        }
        #pragma unroll
        for (int j = 0; j < 8; j++) {
            u64 pa0 = pack2(pv0[j], pv0[j]);
            u64 pa1 = pack2(pv1[j], pv1[j]);
            fma2(acc2[0][0], pa0, ev[j].x); fma2(acc2[0][1], pa0, ev[j].y);
            fma2(acc2[1][0], pa1, ev[j].x); fma2(acc2[1][1], pa1, ev[j].y);
        }
    }

    #pragma unroll
    for (int i = 0; i < 2; i++) {
        float l0, h0, l1, h1;
        unpack2(acc2[i][0], l0, h0);
        unpack2(acc2[i][1], l1, h1);
        float4 r = {l0, h0, l1, h1};
        *(float4*)&co[(size_t)(b * TT + db * 16 + m0 + i) * HH + n0] = r;
    }
}

// ---------------------------------------------------------------------------
extern "C" void kernel_launch(void* const* d_in, const int* in_sizes, int n_in,
                              void* d_out, int out_size) {
    const float* enc = (const float*)d_in[0];
    const float* dec = (const float*)d_in[1];
    const float* Wa  = (const float*)d_in[2];
    const float* Ua  = (const float*)d_in[3];
    const float* Va  = (const float*)d_in[4];

    float* co = (float*)d_out;                    // c_outputs [16,128,256]
    float* eo = co + Bsz * TT * HH;               // e_outputs [16,128,128]

    const int SM3 = 131072 + 8192;                // 139264 B
    static bool attr_done = false;
    if (!attr_done) {
        cudaFuncSetAttribute(energy_ctx_kernel,
                             cudaFuncAttributeMaxDynamicSharedMemorySize, SM3);
        attr_done = true;
    }

    ortho_kernel<<<dim3(8, 16), 256>>>(enc);
    gemm2_kernel<<<dim3(16, 4, 2), 256>>>(dec, Wa, Ua);
    energy_ctx_kernel<<<dim3(8, 16), 512, SM3>>>(Va, eo, co);
}